// round 2
// baseline (speedup 1.0000x reference)
#include <cuda_runtime.h>

// ESN recurrence on GB300: persistent grid, weights pinned in SMEM,
// per-step grid barrier via monotonic sum-counter, x exchanged through L2.

#define H        1024
#define T        50000
#define WASHOUT  200
#define NOUT     (T - WASHOUT)   // 49800
#define B        128             // CTAs (<= 148 SMs -> co-resident, spin-safe)
#define R        (H / B)         // 8 rows per CTA
#define THREADS  256             // 8 warps, 1 warp per row

// Persistent device state (no allocations allowed)
__device__ float    g_x[2][H];           // double-buffered state vector
__device__ float    g_coef[H];           // coef[mask[h]] = w_out[h]
__device__ unsigned g_count;             // sum-barrier counter
__device__ float    g_part[(size_t)B * NOUT];  // per-CTA readout partials (~25.5MB)

// ---------------------------------------------------------------------------
// Prologue: reset barrier, zero x0, build coef scatter. 1 block x 1024 threads.
// The mask's on-device dtype is probed at runtime (int32 vs int64): view the
// buffer as int32[1024] (in-bounds under BOTH interpretations). An int64
// permutation of 0..1023 has all-zero high words at every odd int32 slot
// (>=512 zeros); an int32 permutation has exactly one zero total.
// ---------------------------------------------------------------------------
__global__ void esn_prologue(const float* __restrict__ w_out,
                             const void* __restrict__ mask_raw) {
    __shared__ int s_is64;
    const int* m32 = (const int*)mask_raw;
    const int t = threadIdx.x;           // 0..1023

    if (t == 0) {
        int zeros = 0;
        for (int i = 1; i < 1024; i += 2) zeros += (m32[i] == 0);
        s_is64 = (zeros >= 256);
        g_count = 0u;
    }
    __syncthreads();

    int idx;
    if (s_is64) idx = (int)((const long long*)mask_raw)[t];  // 8KB buffer: safe
    else        idx = m32[t];                                // 4KB buffer: safe
    g_coef[idx & 1023] = w_out[t];       // & 1023: scatter can never fault
    g_x[0][t] = 0.0f;
}

// ---------------------------------------------------------------------------
// Main persistent kernel: each CTA owns R=8 rows of w_res in SMEM.
// Per step: sum-barrier wait -> reload x via L2 (__ldcg; L1 is stale across
// steps) -> 8 warp-parallel dot products from SMEM -> tanh -> publish slice
// -> release fence -> atomicAdd arrive.
// ---------------------------------------------------------------------------
__global__ void __launch_bounds__(THREADS, 1)
esn_main(const float* __restrict__ u,
         const float* __restrict__ w_in,
         const float* __restrict__ w_res) {
    __shared__ float s_w[R][H];          // 32 KB weight slice
    __shared__ float s_x[H];             // 4 KB state
    __shared__ float s_val[R];

    const int tid  = threadIdx.x;
    const int cta  = blockIdx.x;
    const int row0 = cta * R;
    const int warp = tid >> 5;
    const int lane = tid & 31;

    // Pin this CTA's weight rows in SMEM (one-time DRAM read: 4 MB chip-wide)
    {
        const float4* wsrc = reinterpret_cast<const float4*>(w_res + (size_t)row0 * H);
        float4*       wdst = reinterpret_cast<float4*>(&s_w[0][0]);
        #pragma unroll
        for (int i = tid; i < R * H / 4; i += THREADS)
            wdst[i] = wsrc[i];
    }
    const float my_win  = w_in[row0 + warp];    // row = row0 + warp
    const float my_coef = g_coef[row0 + warp];
    __syncthreads();

    volatile unsigned* vcnt = &g_count;

    for (int k = 0; k < T; ++k) {
        // ---- barrier: wait until every CTA published x_k -------------------
        if (tid == 0) {
            if (k > 0) {
                const unsigned target = (unsigned)k * (unsigned)B;
                while (*vcnt < target) { /* spin on L2 */ }
            }
            __threadfence();             // acquire: make peers' x stores visible
        }
        __syncthreads();

        // ---- reload x_k (L2, bypass stale L1) ------------------------------
        {
            const float4* xin = reinterpret_cast<const float4*>(g_x[k & 1]);
            float4 v = __ldcg(xin + tid);            // 256 thr x float4 = 1024
            reinterpret_cast<float4*>(s_x)[tid] = v;
        }
        __syncthreads();

        // ---- warp-per-row dot product from SMEM ----------------------------
        const float4* wrow = reinterpret_cast<const float4*>(&s_w[warp][0]);
        const float4* xr   = reinterpret_cast<const float4*>(s_x);
        float acc = 0.0f;
        #pragma unroll
        for (int j = 0; j < 8; ++j) {
            float4 a = wrow[lane + 32 * j];
            float4 b = xr  [lane + 32 * j];
            acc = fmaf(a.x, b.x, acc);
            acc = fmaf(a.y, b.y, acc);
            acc = fmaf(a.z, b.z, acc);
            acc = fmaf(a.w, b.w, acc);
        }
        #pragma unroll
        for (int off = 16; off > 0; off >>= 1)
            acc += __shfl_xor_sync(0xffffffffu, acc, off);

        if (lane == 0) {
            float val = tanhf(fmaf(my_win, __ldg(u + k), acc));
            g_x[(k + 1) & 1][row0 + warp] = val;     // publish slice of x_{k+1}
            s_val[warp] = val * my_coef;             // readout contribution
        }
        __syncthreads();

        // ---- readout partial + release + arrive ----------------------------
        if (tid == 0) {
            if (k >= WASHOUT) {
                float p = 0.0f;
                #pragma unroll
                for (int r = 0; r < R; ++r) p += s_val[r];
                g_part[(size_t)cta * NOUT + (k - WASHOUT)] = p;
            }
            __threadfence();             // release: x slice visible before arrive
            atomicAdd(&g_count, 1u);
        }
    }
}

// ---------------------------------------------------------------------------
// Finalize: deterministic fixed-order reduction of per-CTA partials.
// ---------------------------------------------------------------------------
__global__ void esn_finalize(float* __restrict__ out) {
    int t = blockIdx.x * blockDim.x + threadIdx.x;
    if (t < NOUT) {
        float s = 0.0f;
        #pragma unroll 8
        for (int b = 0; b < B; ++b)
            s += g_part[(size_t)b * NOUT + t];       // coalesced across threads
        out[t] = s;
    }
}

// ---------------------------------------------------------------------------
// Launch: prologue -> persistent mainloop -> finalize (all graph-capturable).
// Inputs (metadata order): u[50000] f32, w_in[1024] f32, w_res[1024*1024] f32,
// w_out[1024] f32, w_out_mask[1024] int (32 or 64; probed). Output: 49800 f32.
// ---------------------------------------------------------------------------
extern "C" void kernel_launch(void* const* d_in, const int* in_sizes, int n_in,
                              void* d_out, int out_size) {
    const float* u     = (const float*)d_in[0];
    const float* w_in  = (const float*)d_in[1];
    const float* w_res = (const float*)d_in[2];
    const float* w_out = (const float*)d_in[3];
    const void*  mask  = d_in[4];
    float*       out   = (float*)d_out;

    esn_prologue<<<1, 1024>>>(w_out, mask);
    esn_main<<<B, THREADS>>>(u, w_in, w_res);
    esn_finalize<<<(NOUT + 255) / 256, 256>>>(out);
}